// round 13
// baseline (speedup 1.0000x reference)
#include <cuda_runtime.h>
#include <cuda_bf16.h>
#include <math.h>
#include <stdint.h>

// Problem constants
#define Bsz 16
#define CIn 32
#define COn 32
#define Hn  256
#define Wn  256
#define KM  32
#define SXn 64
#define RTOT (Bsz*CIn*Hn)   // 131072 rows

// ============================ tables ============================
__device__ float2 g_TV [64*32];   // [sx][v] e^{-2pi i kx(sx) v/256}
__device__ float2 g_E8 [8*8];
__device__ float2 g_E8i[8*8];
// fwdW basis  [kc(4)][n(64)][72pad]  bf16 hi/lo (smem-staged per chunk — R6 style)
__device__ __align__(16) __nv_bfloat16 g_BWh[4*64*72], g_BWl[4*64*72];
// irfft basis [nh(2)][wn(128)][72pad] bf16 hi/lo (smem-staged — R6 style)
__device__ __align__(16) __nv_bfloat16 g_BIh[2*128*72], g_BIl[2*128*72];

// ============================ scratch ============================
__device__ float2 g_Xw[(size_t)RTOT*KM];          // fwdW out [row][k]
__device__ float2 g_Xf[(size_t)Bsz*CIn*SXn*KM];   // fwdH out [bci][sx][k]
__device__ float2 g_Of[(size_t)Bsz*COn*SXn*KM];   // mix out  [bco][sx][k]
// invH out, bf16 hi/lo planes in irfftW's A layout: [row][64] = interleaved (re,im) per ky
__device__ __align__(16) __nv_bfloat16 g_TmpAh[(size_t)Bsz*COn*Hn*64];
__device__ __align__(16) __nv_bfloat16 g_TmpAl[(size_t)Bsz*COn*Hn*64];
__device__ float2 g_Wt [2*1024*1024];
__device__ float2 g_Wet[2*1024*1024];

// ============================ helpers ============================
__device__ __forceinline__ uint32_t pack_bf(__nv_bfloat16 a, __nv_bfloat16 b) {
    return (uint32_t)__bfloat16_as_ushort(a) | ((uint32_t)__bfloat16_as_ushort(b) << 16);
}
__device__ __forceinline__ void split_bf(float v, __nv_bfloat16& h, __nv_bfloat16& l) {
    h = __float2bfloat16(v);
    l = __float2bfloat16(v - __bfloat162float(h));
}
__device__ __forceinline__ void mma16816(float* c, const uint32_t* a, const uint32_t* b) {
    asm volatile("mma.sync.aligned.m16n8k16.row.col.f32.bf16.bf16.f32 "
        "{%0,%1,%2,%3}, {%4,%5,%6,%7}, {%8,%9}, {%0,%1,%2,%3};"
        : "+f"(c[0]), "+f"(c[1]), "+f"(c[2]), "+f"(c[3])
        : "r"(a[0]), "r"(a[1]), "r"(a[2]), "r"(a[3]), "r"(b[0]), "r"(b[1]));
}

#define SEG 18432   // 4*64*72 == 2*128*72

__global__ void k_init() {
    int t = blockIdx.x * blockDim.x + threadIdx.x;
    if (t < 2048) {                     // g_TV
        int sx = t >> 5, v = t & 31;
        int kx = (sx < 32) ? sx : (192 + sx);
        float s, c; sincospif((float)(kx * v) / 128.0f, &s, &c);
        g_TV[t] = make_float2(c, -s);
    }
    int t1 = t - 2048;
    if (t1 >= 0 && t1 < 64) {           // E8 / E8i
        int m = t1 >> 3, a = t1 & 7;
        float s, c; sincospif((float)(m * a) / 4.0f, &s, &c);
        g_E8 [t1] = make_float2(c, -s);
        g_E8i[t1] = make_float2(c,  s);
    }
    int t2 = t1 - 64;
    if (t2 >= 0 && t2 < SEG) {          // fwdW basis
        int kc = t2 / (64*72);
        int rem = t2 % (64*72);
        int n = rem / 72, kk = rem % 72;
        float v = 0.f;
        if (kk < 64) {
            int w = kc * 64 + kk;
            float s, c; sincospif((float)((n >> 1) * w) / 128.0f, &s, &c);
            v = (n & 1) ? -s : c;
        }
        __nv_bfloat16 h, l; split_bf(v, h, l);
        g_BWh[t2] = h; g_BWl[t2] = l;
    }
    int t3 = t2 - SEG;
    if (t3 >= 0 && t3 < SEG) {          // irfft basis
        int nh = t3 / (128*72);
        int rem = t3 % (128*72);
        int wn = rem / 72, j = rem % 72;
        float v = 0.f;
        if (j < 64) {
            int w = nh * 128 + wn;
            int q = j >> 1;
            float s, c; sincospif((float)(q * w) / 128.0f, &s, &c);
            float alpha = ((q == 0) ? 1.0f : 2.0f) * (1.0f / 256.0f);
            v = (j & 1) ? -alpha * s : alpha * c;
        }
        __nv_bfloat16 h, l; split_bf(v, h, l);
        g_BIh[t3] = h; g_BIl[t3] = l;
    }
}

// ---- K0b: transpose weights [p][kxy] -> [kxy][p] ----
__global__ void __launch_bounds__(256) k_wtrans(const float* __restrict__ w0,
                                                const float* __restrict__ w1,
                                                const float* __restrict__ we0,
                                                const float* __restrict__ we1) {
    __shared__ float2 sm[32][33];
    int bid = blockIdx.x;
    int arr = bid >> 10;
    int tile = bid & 1023;
    int I = tile >> 5, J = tile & 31;
    const float2* src = (const float2*)((arr == 0) ? w0 : (arr == 1) ? w1 : (arr == 2) ? we0 : we1);
    float2* dst = (arr < 2) ? (g_Wt + (size_t)arr * 1024 * 1024)
                            : (g_Wet + (size_t)(arr - 2) * 1024 * 1024);
    int t = threadIdx.x;
    int c = t & 31, rq = t >> 5;
    #pragma unroll
    for (int i = 0; i < 4; i++)
        sm[rq + 8 * i][c] = src[(size_t)(I * 32 + rq + 8 * i) * 1024 + J * 32 + c];
    __syncthreads();
    #pragma unroll
    for (int i = 0; i < 4; i++)
        dst[(size_t)(J * 32 + rq + 8 * i) * 1024 + I * 32 + c] = sm[c][rq + 8 * i];
}

// ============== K1: fwd DFT along W via mma.sync (R6 verbatim) ==============
#define FW_SMEM 55296
__global__ void __launch_bounds__(256) k_fwdW_m(const float* __restrict__ x) {
    extern __shared__ unsigned char smem[];
    __nv_bfloat16* Ah = (__nv_bfloat16*)(smem);
    __nv_bfloat16* Al = (__nv_bfloat16*)(smem + 18432);
    __nv_bfloat16* Bh = (__nv_bfloat16*)(smem + 36864);
    __nv_bfloat16* Bl = (__nv_bfloat16*)(smem + 46080);
    int tid = threadIdx.x, lane = tid & 31, wid = tid >> 5;
    int g = lane >> 2, t4 = lane & 3;
    size_t rowBase = (size_t)blockIdx.x * 128;
    int m0 = wid * 16;
    float acc[8][4];
    #pragma unroll
    for (int nt = 0; nt < 8; nt++)
        #pragma unroll
        for (int i = 0; i < 4; i++) acc[nt][i] = 0.f;

    const float4* xg = (const float4*)x;
    for (int kc = 0; kc < 4; kc++) {
        __syncthreads();
        #pragma unroll
        for (int i = 0; i < 8; i++) {
            int idx = tid + 256 * i;
            int r = idx >> 4, c4 = idx & 15;
            float4 v = xg[(rowBase + r) * 64 + kc * 16 + c4];
            __nv_bfloat16 h0, h1, h2, h3, l0, l1, l2, l3;
            split_bf(v.x, h0, l0); split_bf(v.y, h1, l1);
            split_bf(v.z, h2, l2); split_bf(v.w, h3, l3);
            *(uint2*)(Ah + r * 72 + c4 * 4) = make_uint2(pack_bf(h0, h1), pack_bf(h2, h3));
            *(uint2*)(Al + r * 72 + c4 * 4) = make_uint2(pack_bf(l0, l1), pack_bf(l2, l3));
        }
        {
            const uint4* sh = ((const uint4*)g_BWh) + kc * 576;
            const uint4* sl = ((const uint4*)g_BWl) + kc * 576;
            uint4* dh = (uint4*)Bh; uint4* dl = (uint4*)Bl;
            for (int i = tid; i < 576; i += 256) { dh[i] = sh[i]; dl[i] = sl[i]; }
        }
        __syncthreads();
        #pragma unroll
        for (int ks = 0; ks < 4; ks++) {
            int aoff = (m0 + g) * 72 + ks * 16 + 2 * t4;
            uint32_t ah[4], al[4];
            ah[0] = *(const uint32_t*)(Ah + aoff);
            ah[1] = *(const uint32_t*)(Ah + aoff + 8 * 72);
            ah[2] = *(const uint32_t*)(Ah + aoff + 8);
            ah[3] = *(const uint32_t*)(Ah + aoff + 8 * 72 + 8);
            al[0] = *(const uint32_t*)(Al + aoff);
            al[1] = *(const uint32_t*)(Al + aoff + 8 * 72);
            al[2] = *(const uint32_t*)(Al + aoff + 8);
            al[3] = *(const uint32_t*)(Al + aoff + 8 * 72 + 8);
            #pragma unroll
            for (int nt = 0; nt < 8; nt++) {
                int boff = (nt * 8 + g) * 72 + ks * 16 + 2 * t4;
                uint32_t bh[2], bl[2];
                bh[0] = *(const uint32_t*)(Bh + boff);
                bh[1] = *(const uint32_t*)(Bh + boff + 8);
                bl[0] = *(const uint32_t*)(Bl + boff);
                bl[1] = *(const uint32_t*)(Bl + boff + 8);
                mma16816(acc[nt], ah, bh);
                mma16816(acc[nt], ah, bl);
                mma16816(acc[nt], al, bh);
            }
        }
    }
    float2* gx = (float2*)g_Xw;
    #pragma unroll
    for (int nt = 0; nt < 8; nt++) {
        int col = nt * 4 + t4;
        gx[(rowBase + m0 + g) * 32 + col]     = make_float2(acc[nt][0], acc[nt][1]);
        gx[(rowBase + m0 + g + 8) * 32 + col] = make_float2(acc[nt][2], acc[nt][3]);
    }
}

// ---- K2: fwd DFT along H (scalar radix-8) — PADDED smem, conflict-free ----
__global__ void __launch_bounds__(256) k_fwdH() {
    __shared__ float2 Xs[256 * 9];        // row stride 9 (was 8)
    __shared__ float2 Ys[32 * 73];        // v stride 73, m stride 9 (was 64 / 8)
    __shared__ float2 E8s[8][8];
    int t = threadIdx.x;
    int bci = blockIdx.x >> 2, kq = blockIdx.x & 3;
    const float2* Xp = g_Xw + (size_t)bci * 256 * 32 + kq * 8;
    #pragma unroll
    for (int i = 0; i < 8; i++) {
        int idx = t + 256*i;
        Xs[(idx >> 3) * 9 + (idx & 7)] = Xp[(size_t)(idx >> 3) * 32 + (idx & 7)];
    }
    if (t < 64) ((float2*)E8s)[t] = g_E8[t];
    __syncthreads();
    int v = t >> 3, k = t & 7;
    {
        float2 xa[8];
        #pragma unroll
        for (int a = 0; a < 8; a++) xa[a] = Xs[(v + 32*a) * 9 + k];
        #pragma unroll
        for (int m = 0; m < 8; m++) {
            float yr = 0.f, yi = 0.f;
            #pragma unroll
            for (int a = 0; a < 8; a++) {
                float2 e = E8s[m][a];
                yr = fmaf(xa[a].x, e.x, fmaf(-xa[a].y, e.y, yr));
                yi = fmaf(xa[a].x, e.y, fmaf( xa[a].y, e.x, yi));
            }
            Ys[v * 73 + m * 9 + k] = make_float2(yr, yi);
        }
    }
    __syncthreads();
    int k2 = t & 7, sx2 = t >> 3;
    int m = sx2 & 7;
    float a0x = 0.f, a0y = 0.f, a1x = 0.f, a1y = 0.f;
    #pragma unroll 8
    for (int vv = 0; vv < 32; vv++) {
        float2 y  = Ys[vv * 73 + m * 9 + k2];
        float2 t0 = g_TV[sx2 * 32 + vv];
        float2 t1 = g_TV[(sx2 + 32) * 32 + vv];
        a0x = fmaf(y.x, t0.x, fmaf(-y.y, t0.y, a0x));
        a0y = fmaf(y.x, t0.y, fmaf( y.y, t0.x, a0y));
        a1x = fmaf(y.x, t1.x, fmaf(-y.y, t1.y, a1x));
        a1y = fmaf(y.x, t1.y, fmaf( y.y, t1.x, a1y));
    }
    const float nrm = 1.0f / 256.0f;
    g_Xf[((size_t)bci * 64 + sx2)      * 32 + kq * 8 + k2] = make_float2(a0x * nrm, a0y * nrm);
    g_Xf[((size_t)bci * 64 + sx2 + 32) * 32 + kq * 8 + k2] = make_float2(a1x * nrm, a1y * nrm);
}

// ---- K3: channel mixing (R6 verbatim) ----
__global__ void __launch_bounds__(256) k_mix(const float* __restrict__ fs) {
    __shared__ float2 Ws[1024];
    __shared__ float2 Wes[1024];
    __shared__ float2 Xs[16][32];
    __shared__ float  ssm[16];
    int bid = blockIdx.x;
    int r = bid >> 10, kxy = bid & 1023;
    int kx = kxy >> 5, ky = kxy & 31;
    int sxg = r * 32 + kx;
    const float2* Wp  = g_Wt  + ((size_t)r << 20) + ((size_t)kxy << 10);
    const float2* Wep = g_Wet + ((size_t)r << 20) + ((size_t)kxy << 10);
    int t = threadIdx.x;
    #pragma unroll
    for (int i = 0; i < 4; i++) {
        Ws [t + 256*i] = Wp [t + 256*i];
        Wes[t + 256*i] = Wep[t + 256*i];
    }
    #pragma unroll
    for (int i = 0; i < 2; i++) {
        int p = t + 256*i;
        Xs[p >> 5][p & 31] = g_Xf[((size_t)p * 64 + sxg) * 32 + ky];
    }
    if (t < 16) {
        int idx;
        if (kx < 8 && ky < 8)        idx = 0;
        else if (kx < 16 && ky < 16) idx = (kx < 8) ? 1 : ((ky < 8) ? 2 : 3);
        else                         idx = (kx < 16) ? 4 : ((ky < 16) ? 5 : 6);
        ssm[t] = fs[t * 7 + idx];
    }
    __syncthreads();
    int co = t & 31, bh = t >> 5;
    float sb0 = ssm[bh], sb1 = ssm[bh + 8];
    float a0x = 0.f, a0y = 0.f, a1x = 0.f, a1y = 0.f;
    #pragma unroll 8
    for (int ci = 0; ci < 32; ci++) {
        float2 w  = Ws [ci * 32 + co];
        float2 we = Wes[ci * 32 + co];
        float2 x0 = Xs[bh][ci];
        float2 x1 = Xs[bh + 8][ci];
        float wr0 = fmaf(sb0, we.x, w.x), wi0 = fmaf(sb0, we.y, w.y);
        float wr1 = fmaf(sb1, we.x, w.x), wi1 = fmaf(sb1, we.y, w.y);
        a0x = fmaf(x0.x, wr0, fmaf(-x0.y, wi0, a0x));
        a0y = fmaf(x0.x, wi0, fmaf( x0.y, wr0, a0y));
        a1x = fmaf(x1.x, wr1, fmaf(-x1.y, wi1, a1x));
        a1y = fmaf(x1.x, wi1, fmaf( x1.y, wr1, a1y));
    }
    g_Of[(((size_t)bh       * 32 + co) * 64 + sxg) * 32 + ky] = make_float2(a0x, a0y);
    g_Of[(((size_t)(bh + 8) * 32 + co) * 64 + sxg) * 32 + ky] = make_float2(a1x, a1y);
}

// ---- K4: inverse DFT along H (scalar radix-8); emits bf16 hi/lo planes ----
__global__ void __launch_bounds__(256) k_invH() {
    __shared__ float2 Ofs[64][8];
    __shared__ float2 E8is[8][8];
    int t = threadIdx.x;
    int bco = blockIdx.x >> 2, kq = blockIdx.x & 3;
    const float2* Op = g_Of + (size_t)bco * 64 * 32 + kq * 8;
    #pragma unroll
    for (int i = 0; i < 2; i++) {
        int idx = t + 256*i;
        Ofs[idx >> 3][idx & 7] = Op[(size_t)(idx >> 3) * 32 + (idx & 7)];
    }
    if (t < 64) ((float2*)E8is)[t] = g_E8i[t];
    __syncthreads();
    int v = t >> 3, k = t & 7;
    float2 gg[8];
    #pragma unroll
    for (int m = 0; m < 8; m++) {
        float gx = 0.f, gy = 0.f;
        #pragma unroll
        for (int j = 0; j < 8; j++) {
            int sx = m + 8*j;
            float2 o  = Ofs[sx][k];
            float2 tw = g_TV[sx * 32 + v];
            gx = fmaf(o.x, tw.x, fmaf( o.y, tw.y, gx));
            gy = fmaf(o.y, tw.x, fmaf(-o.x, tw.y, gy));
        }
        gg[m] = make_float2(gx, gy);
    }
    int col = kq * 8 + k;
    #pragma unroll
    for (int a = 0; a < 8; a++) {
        float tx = 0.f, ty = 0.f;
        #pragma unroll
        for (int m = 0; m < 8; m++) {
            float2 e = E8is[m][a];
            tx = fmaf(gg[m].x, e.x, fmaf(-gg[m].y, e.y, tx));
            ty = fmaf(gg[m].x, e.y, fmaf( gg[m].y, e.x, ty));
        }
        size_t row = (size_t)bco * 256 + v + 32 * a;
        __nv_bfloat16 hr, lr, hi, li;
        split_bf(tx, hr, lr); split_bf(ty, hi, li);
        *(uint32_t*)(g_TmpAh + row * 64 + 2 * col) = pack_bf(hr, hi);
        *(uint32_t*)(g_TmpAl + row * 64 + 2 * col) = pack_bf(lr, li);
    }
}

// ============== K5: inverse real DFT along W via mma.sync; A = pure memcpy ==============
#define IR_SMEM 73728
__global__ void __launch_bounds__(256) k_irfftW_m(float* __restrict__ out) {
    extern __shared__ unsigned char smem[];
    __nv_bfloat16* Ah = (__nv_bfloat16*)(smem);             // [128][72 pad]
    __nv_bfloat16* Al = (__nv_bfloat16*)(smem + 18432);
    __nv_bfloat16* Bh = (__nv_bfloat16*)(smem + 36864);
    __nv_bfloat16* Bl = (__nv_bfloat16*)(smem + 55296);
    int tid = threadIdx.x, lane = tid & 31, wid = tid >> 5;
    int g = lane >> 2, t4 = lane & 3;
    int rg = blockIdx.x >> 1, nh = blockIdx.x & 1;
    size_t rowBase = (size_t)rg * 128;

    // stage A: pure uint4 memcpy with pad (planes already bf16 in A layout)
    {
        const uint4* sh = (const uint4*)(g_TmpAh + rowBase * 64);
        const uint4* sl = (const uint4*)(g_TmpAl + rowBase * 64);
        #pragma unroll
        for (int i = 0; i < 4; i++) {
            int idx = tid + 256 * i;              // 1024 = 128 rows x 8 uint4
            int row = idx >> 3, c = idx & 7;
            *(uint4*)(Ah + row * 72 + c * 8) = sh[idx];
            *(uint4*)(Al + row * 72 + c * 8) = sl[idx];
        }
    }
    // stage B: constant basis half (R6 style contiguous copy)
    {
        const uint4* sh = ((const uint4*)g_BIh) + nh * 1152;
        const uint4* sl = ((const uint4*)g_BIl) + nh * 1152;
        uint4* dh = (uint4*)Bh; uint4* dl = (uint4*)Bl;
        for (int i = tid; i < 1152; i += 256) { dh[i] = sh[i]; dl[i] = sl[i]; }
    }
    __syncthreads();

    int m0 = (wid >> 1) * 32;
    int n0 = (wid & 1) * 64;
    float acc[2][8][4];
    #pragma unroll
    for (int mt = 0; mt < 2; mt++)
        #pragma unroll
        for (int nt = 0; nt < 8; nt++)
            #pragma unroll
            for (int i = 0; i < 4; i++) acc[mt][nt][i] = 0.f;

    #pragma unroll
    for (int ks = 0; ks < 4; ks++) {
        uint32_t ah[2][4], al[2][4];
        #pragma unroll
        for (int mt = 0; mt < 2; mt++) {
            int aoff = (m0 + mt * 16 + g) * 72 + ks * 16 + 2 * t4;
            ah[mt][0] = *(const uint32_t*)(Ah + aoff);
            ah[mt][1] = *(const uint32_t*)(Ah + aoff + 8 * 72);
            ah[mt][2] = *(const uint32_t*)(Ah + aoff + 8);
            ah[mt][3] = *(const uint32_t*)(Ah + aoff + 8 * 72 + 8);
            al[mt][0] = *(const uint32_t*)(Al + aoff);
            al[mt][1] = *(const uint32_t*)(Al + aoff + 8 * 72);
            al[mt][2] = *(const uint32_t*)(Al + aoff + 8);
            al[mt][3] = *(const uint32_t*)(Al + aoff + 8 * 72 + 8);
        }
        #pragma unroll
        for (int nt = 0; nt < 8; nt++) {
            int boff = (n0 + nt * 8 + g) * 72 + ks * 16 + 2 * t4;
            uint32_t bh[2], bl[2];
            bh[0] = *(const uint32_t*)(Bh + boff);
            bh[1] = *(const uint32_t*)(Bh + boff + 8);
            bl[0] = *(const uint32_t*)(Bl + boff);
            bl[1] = *(const uint32_t*)(Bl + boff + 8);
            #pragma unroll
            for (int mt = 0; mt < 2; mt++) {
                mma16816(acc[mt][nt], ah[mt], bh);
                mma16816(acc[mt][nt], ah[mt], bl);
                mma16816(acc[mt][nt], al[mt], bh);
            }
        }
    }
    #pragma unroll
    for (int mt = 0; mt < 2; mt++) {
        size_t r0 = rowBase + m0 + mt * 16 + g;
        #pragma unroll
        for (int nt = 0; nt < 8; nt++) {
            int col = nh * 128 + n0 + nt * 8 + 2 * t4;
            *(float2*)(out + r0 * 256 + col)       = make_float2(acc[mt][nt][0], acc[mt][nt][1]);
            *(float2*)(out + (r0 + 8) * 256 + col) = make_float2(acc[mt][nt][2], acc[mt][nt][3]);
        }
    }
}

extern "C" void kernel_launch(void* const* d_in, const int* in_sizes, int n_in,
                              void* d_out, int out_size) {
    const float* x   = (const float*)d_in[0];
    const float* fs  = (const float*)d_in[1];
    const float* w0  = (const float*)d_in[2];
    const float* w1  = (const float*)d_in[3];
    const float* we0 = (const float*)d_in[4];
    const float* we1 = (const float*)d_in[5];
    float* out = (float*)d_out;

    cudaFuncSetAttribute(k_fwdW_m,   cudaFuncAttributeMaxDynamicSharedMemorySize, FW_SMEM);
    cudaFuncSetAttribute(k_irfftW_m, cudaFuncAttributeMaxDynamicSharedMemorySize, IR_SMEM);

    k_init<<<153, 256>>>();
    k_wtrans<<<4096, 256>>>(w0, w1, we0, we1);
    k_fwdW_m<<<RTOT / 128, 256, FW_SMEM>>>(x);        // 1024 CTAs
    k_fwdH<<<Bsz * CIn * 4, 256>>>();                 // 2048 CTAs
    k_mix<<<2 * 1024, 256>>>(fs);                     // 2048 CTAs
    k_invH<<<Bsz * COn * 4, 256>>>();                 // 2048 CTAs
    k_irfftW_m<<<RTOT / 64, 256, IR_SMEM>>>(out);     // 2048 CTAs
}

// round 14
// speedup vs baseline: 1.0464x; 1.0464x over previous
#include <cuda_runtime.h>
#include <cuda_bf16.h>
#include <math.h>
#include <stdint.h>

// Problem constants
#define Bsz 16
#define CIn 32
#define COn 32
#define Hn  256
#define Wn  256
#define KM  32
#define SXn 64
#define RTOT (Bsz*CIn*Hn)   // 131072 rows

// ============================ tables ============================
__device__ float2 g_TV [64*32];   // [sx][v] e^{-2pi i kx(sx) v/256}  (invH)
__device__ float4 g_TV2[32*32];   // [sx2][v] packed (TV[sx2][v], TV[sx2+32][v])  (fwdH)
__device__ float2 g_E8 [8*8];
__device__ float2 g_E8i[8*8];
// fwdW basis  [kc(4)][n(64)][72pad]  bf16 hi/lo (smem-staged per chunk)
__device__ __align__(16) __nv_bfloat16 g_BWh[4*64*72], g_BWl[4*64*72];
// irfft basis [nh(2)][wn(128)][72pad] bf16 hi/lo (smem-staged)
__device__ __align__(16) __nv_bfloat16 g_BIh[2*128*72], g_BIl[2*128*72];

// ============================ scratch ============================
__device__ float2 g_Xw[(size_t)RTOT*KM];          // fwdW out [row][k]
__device__ float2 g_Xf[(size_t)Bsz*CIn*SXn*KM];   // fwdH out [bci][sx][k]
__device__ float2 g_Of[(size_t)Bsz*COn*SXn*KM];   // mix out  [bco][sx][k]
// invH out, bf16 hi/lo planes in irfftW's A layout: [row][64] = interleaved (re,im) per ky
__device__ __align__(16) __nv_bfloat16 g_TmpAh[(size_t)Bsz*COn*Hn*64];
__device__ __align__(16) __nv_bfloat16 g_TmpAl[(size_t)Bsz*COn*Hn*64];
__device__ float2 g_Wt [2*1024*1024];
__device__ float2 g_Wet[2*1024*1024];

// ============================ helpers ============================
__device__ __forceinline__ uint32_t pack_bf(__nv_bfloat16 a, __nv_bfloat16 b) {
    return (uint32_t)__bfloat16_as_ushort(a) | ((uint32_t)__bfloat16_as_ushort(b) << 16);
}
__device__ __forceinline__ void split_bf(float v, __nv_bfloat16& h, __nv_bfloat16& l) {
    h = __float2bfloat16(v);
    l = __float2bfloat16(v - __bfloat162float(h));
}
__device__ __forceinline__ void mma16816(float* c, const uint32_t* a, const uint32_t* b) {
    asm volatile("mma.sync.aligned.m16n8k16.row.col.f32.bf16.bf16.f32 "
        "{%0,%1,%2,%3}, {%4,%5,%6,%7}, {%8,%9}, {%0,%1,%2,%3};"
        : "+f"(c[0]), "+f"(c[1]), "+f"(c[2]), "+f"(c[3])
        : "r"(a[0]), "r"(a[1]), "r"(a[2]), "r"(a[3]), "r"(b[0]), "r"(b[1]));
}

#define SEG 18432   // 4*64*72 == 2*128*72

__global__ void k_init() {
    int t = blockIdx.x * blockDim.x + threadIdx.x;
    if (t < 2048) {                     // g_TV
        int sx = t >> 5, v = t & 31;
        int kx = (sx < 32) ? sx : (192 + sx);
        float s, c; sincospif((float)(kx * v) / 128.0f, &s, &c);
        g_TV[t] = make_float2(c, -s);
    }
    if (t >= 2048 && t < 3072) {        // g_TV2 packed (sx2, sx2+32)
        int e = t - 2048;
        int sx2 = e >> 5, v = e & 31;
        float s0, c0, s1, c1;
        sincospif((float)(sx2 * v) / 128.0f, &s0, &c0);
        int kx1 = 224 + sx2;            // kx for sx2+32
        sincospif((float)(kx1 * v) / 128.0f, &s1, &c1);
        g_TV2[e] = make_float4(c0, -s0, c1, -s1);
    }
    int t1 = t - 3072;
    if (t1 >= 0 && t1 < 64) {           // E8 / E8i
        int m = t1 >> 3, a = t1 & 7;
        float s, c; sincospif((float)(m * a) / 4.0f, &s, &c);
        g_E8 [t1] = make_float2(c, -s);
        g_E8i[t1] = make_float2(c,  s);
    }
    int t2 = t1 - 64;
    if (t2 >= 0 && t2 < SEG) {          // fwdW basis
        int kc = t2 / (64*72);
        int rem = t2 % (64*72);
        int n = rem / 72, kk = rem % 72;
        float v = 0.f;
        if (kk < 64) {
            int w = kc * 64 + kk;
            float s, c; sincospif((float)((n >> 1) * w) / 128.0f, &s, &c);
            v = (n & 1) ? -s : c;
        }
        __nv_bfloat16 h, l; split_bf(v, h, l);
        g_BWh[t2] = h; g_BWl[t2] = l;
    }
    int t3 = t2 - SEG;
    if (t3 >= 0 && t3 < SEG) {          // irfft basis
        int nh = t3 / (128*72);
        int rem = t3 % (128*72);
        int wn = rem / 72, j = rem % 72;
        float v = 0.f;
        if (j < 64) {
            int w = nh * 128 + wn;
            int q = j >> 1;
            float s, c; sincospif((float)(q * w) / 128.0f, &s, &c);
            float alpha = ((q == 0) ? 1.0f : 2.0f) * (1.0f / 256.0f);
            v = (j & 1) ? -alpha * s : alpha * c;
        }
        __nv_bfloat16 h, l; split_bf(v, h, l);
        g_BIh[t3] = h; g_BIl[t3] = l;
    }
}

// ---- K0b: transpose weights [p][kxy] -> [kxy][p] ----
__global__ void __launch_bounds__(256) k_wtrans(const float* __restrict__ w0,
                                                const float* __restrict__ w1,
                                                const float* __restrict__ we0,
                                                const float* __restrict__ we1) {
    __shared__ float2 sm[32][33];
    int bid = blockIdx.x;
    int arr = bid >> 10;
    int tile = bid & 1023;
    int I = tile >> 5, J = tile & 31;
    const float2* src = (const float2*)((arr == 0) ? w0 : (arr == 1) ? w1 : (arr == 2) ? we0 : we1);
    float2* dst = (arr < 2) ? (g_Wt + (size_t)arr * 1024 * 1024)
                            : (g_Wet + (size_t)(arr - 2) * 1024 * 1024);
    int t = threadIdx.x;
    int c = t & 31, rq = t >> 5;
    #pragma unroll
    for (int i = 0; i < 4; i++)
        sm[rq + 8 * i][c] = src[(size_t)(I * 32 + rq + 8 * i) * 1024 + J * 32 + c];
    __syncthreads();
    #pragma unroll
    for (int i = 0; i < 4; i++)
        dst[(size_t)(J * 32 + rq + 8 * i) * 1024 + I * 32 + c] = sm[c][rq + 8 * i];
}

// ============== K1: fwd DFT along W via mma.sync (R6 verbatim) ==============
#define FW_SMEM 55296
__global__ void __launch_bounds__(256) k_fwdW_m(const float* __restrict__ x) {
    extern __shared__ unsigned char smem[];
    __nv_bfloat16* Ah = (__nv_bfloat16*)(smem);
    __nv_bfloat16* Al = (__nv_bfloat16*)(smem + 18432);
    __nv_bfloat16* Bh = (__nv_bfloat16*)(smem + 36864);
    __nv_bfloat16* Bl = (__nv_bfloat16*)(smem + 46080);
    int tid = threadIdx.x, lane = tid & 31, wid = tid >> 5;
    int g = lane >> 2, t4 = lane & 3;
    size_t rowBase = (size_t)blockIdx.x * 128;
    int m0 = wid * 16;
    float acc[8][4];
    #pragma unroll
    for (int nt = 0; nt < 8; nt++)
        #pragma unroll
        for (int i = 0; i < 4; i++) acc[nt][i] = 0.f;

    const float4* xg = (const float4*)x;
    for (int kc = 0; kc < 4; kc++) {
        __syncthreads();
        #pragma unroll
        for (int i = 0; i < 8; i++) {
            int idx = tid + 256 * i;
            int r = idx >> 4, c4 = idx & 15;
            float4 v = xg[(rowBase + r) * 64 + kc * 16 + c4];
            __nv_bfloat16 h0, h1, h2, h3, l0, l1, l2, l3;
            split_bf(v.x, h0, l0); split_bf(v.y, h1, l1);
            split_bf(v.z, h2, l2); split_bf(v.w, h3, l3);
            *(uint2*)(Ah + r * 72 + c4 * 4) = make_uint2(pack_bf(h0, h1), pack_bf(h2, h3));
            *(uint2*)(Al + r * 72 + c4 * 4) = make_uint2(pack_bf(l0, l1), pack_bf(l2, l3));
        }
        {
            const uint4* sh = ((const uint4*)g_BWh) + kc * 576;
            const uint4* sl = ((const uint4*)g_BWl) + kc * 576;
            uint4* dh = (uint4*)Bh; uint4* dl = (uint4*)Bl;
            for (int i = tid; i < 576; i += 256) { dh[i] = sh[i]; dl[i] = sl[i]; }
        }
        __syncthreads();
        #pragma unroll
        for (int ks = 0; ks < 4; ks++) {
            int aoff = (m0 + g) * 72 + ks * 16 + 2 * t4;
            uint32_t ah[4], al[4];
            ah[0] = *(const uint32_t*)(Ah + aoff);
            ah[1] = *(const uint32_t*)(Ah + aoff + 8 * 72);
            ah[2] = *(const uint32_t*)(Ah + aoff + 8);
            ah[3] = *(const uint32_t*)(Ah + aoff + 8 * 72 + 8);
            al[0] = *(const uint32_t*)(Al + aoff);
            al[1] = *(const uint32_t*)(Al + aoff + 8 * 72);
            al[2] = *(const uint32_t*)(Al + aoff + 8);
            al[3] = *(const uint32_t*)(Al + aoff + 8 * 72 + 8);
            #pragma unroll
            for (int nt = 0; nt < 8; nt++) {
                int boff = (nt * 8 + g) * 72 + ks * 16 + 2 * t4;
                uint32_t bh[2], bl[2];
                bh[0] = *(const uint32_t*)(Bh + boff);
                bh[1] = *(const uint32_t*)(Bh + boff + 8);
                bl[0] = *(const uint32_t*)(Bl + boff);
                bl[1] = *(const uint32_t*)(Bl + boff + 8);
                mma16816(acc[nt], ah, bh);
                mma16816(acc[nt], ah, bl);
                mma16816(acc[nt], al, bh);
            }
        }
    }
    float2* gx = (float2*)g_Xw;
    #pragma unroll
    for (int nt = 0; nt < 8; nt++) {
        int col = nt * 4 + t4;
        gx[(rowBase + m0 + g) * 32 + col]     = make_float2(acc[nt][0], acc[nt][1]);
        gx[(rowBase + m0 + g + 8) * 32 + col] = make_float2(acc[nt][2], acc[nt][3]);
    }
}

// ---- K2: fwd DFT along H (scalar radix-8, unpadded R6 indexing + packed TV2 loads) ----
__global__ void __launch_bounds__(256) k_fwdH() {
    __shared__ float2 Xs[256][8];
    __shared__ float2 Ys[32][8][8];
    __shared__ float2 E8s[8][8];
    int t = threadIdx.x;
    int bci = blockIdx.x >> 2, kq = blockIdx.x & 3;
    const float2* Xp = g_Xw + (size_t)bci * 256 * 32 + kq * 8;
    #pragma unroll
    for (int i = 0; i < 8; i++) {
        int idx = t + 256*i;
        Xs[idx >> 3][idx & 7] = Xp[(size_t)(idx >> 3) * 32 + (idx & 7)];
    }
    if (t < 64) ((float2*)E8s)[t] = g_E8[t];
    __syncthreads();
    int v = t >> 3, k = t & 7;
    {
        float2 xa[8];
        #pragma unroll
        for (int a = 0; a < 8; a++) xa[a] = Xs[v + 32*a][k];
        #pragma unroll
        for (int m = 0; m < 8; m++) {
            float yr = 0.f, yi = 0.f;
            #pragma unroll
            for (int a = 0; a < 8; a++) {
                float2 e = E8s[m][a];
                yr = fmaf(xa[a].x, e.x, fmaf(-xa[a].y, e.y, yr));
                yi = fmaf(xa[a].x, e.y, fmaf( xa[a].y, e.x, yi));
            }
            Ys[v][m][k] = make_float2(yr, yi);
        }
    }
    __syncthreads();
    int k2 = t & 7, sx2 = t >> 3;
    int m = sx2 & 7;
    float a0x = 0.f, a0y = 0.f, a1x = 0.f, a1y = 0.f;
    #pragma unroll 8
    for (int vv = 0; vv < 32; vv++) {
        float2 y  = Ys[vv][m][k2];
        float4 tp = g_TV2[sx2 * 32 + vv];   // (t0.re, t0.im, t1.re, t1.im) — one 16B load
        a0x = fmaf(y.x, tp.x, fmaf(-y.y, tp.y, a0x));
        a0y = fmaf(y.x, tp.y, fmaf( y.y, tp.x, a0y));
        a1x = fmaf(y.x, tp.z, fmaf(-y.y, tp.w, a1x));
        a1y = fmaf(y.x, tp.w, fmaf( y.y, tp.z, a1y));
    }
    const float nrm = 1.0f / 256.0f;
    g_Xf[((size_t)bci * 64 + sx2)      * 32 + kq * 8 + k2] = make_float2(a0x * nrm, a0y * nrm);
    g_Xf[((size_t)bci * 64 + sx2 + 32) * 32 + kq * 8 + k2] = make_float2(a1x * nrm, a1y * nrm);
}

// ---- K3: channel mixing (R6 verbatim) ----
__global__ void __launch_bounds__(256) k_mix(const float* __restrict__ fs) {
    __shared__ float2 Ws[1024];
    __shared__ float2 Wes[1024];
    __shared__ float2 Xs[16][32];
    __shared__ float  ssm[16];
    int bid = blockIdx.x;
    int r = bid >> 10, kxy = bid & 1023;
    int kx = kxy >> 5, ky = kxy & 31;
    int sxg = r * 32 + kx;
    const float2* Wp  = g_Wt  + ((size_t)r << 20) + ((size_t)kxy << 10);
    const float2* Wep = g_Wet + ((size_t)r << 20) + ((size_t)kxy << 10);
    int t = threadIdx.x;
    #pragma unroll
    for (int i = 0; i < 4; i++) {
        Ws [t + 256*i] = Wp [t + 256*i];
        Wes[t + 256*i] = Wep[t + 256*i];
    }
    #pragma unroll
    for (int i = 0; i < 2; i++) {
        int p = t + 256*i;
        Xs[p >> 5][p & 31] = g_Xf[((size_t)p * 64 + sxg) * 32 + ky];
    }
    if (t < 16) {
        int idx;
        if (kx < 8 && ky < 8)        idx = 0;
        else if (kx < 16 && ky < 16) idx = (kx < 8) ? 1 : ((ky < 8) ? 2 : 3);
        else                         idx = (kx < 16) ? 4 : ((ky < 16) ? 5 : 6);
        ssm[t] = fs[t * 7 + idx];
    }
    __syncthreads();
    int co = t & 31, bh = t >> 5;
    float sb0 = ssm[bh], sb1 = ssm[bh + 8];
    float a0x = 0.f, a0y = 0.f, a1x = 0.f, a1y = 0.f;
    #pragma unroll 8
    for (int ci = 0; ci < 32; ci++) {
        float2 w  = Ws [ci * 32 + co];
        float2 we = Wes[ci * 32 + co];
        float2 x0 = Xs[bh][ci];
        float2 x1 = Xs[bh + 8][ci];
        float wr0 = fmaf(sb0, we.x, w.x), wi0 = fmaf(sb0, we.y, w.y);
        float wr1 = fmaf(sb1, we.x, w.x), wi1 = fmaf(sb1, we.y, w.y);
        a0x = fmaf(x0.x, wr0, fmaf(-x0.y, wi0, a0x));
        a0y = fmaf(x0.x, wi0, fmaf( x0.y, wr0, a0y));
        a1x = fmaf(x1.x, wr1, fmaf(-x1.y, wi1, a1x));
        a1y = fmaf(x1.x, wi1, fmaf( x1.y, wr1, a1y));
    }
    g_Of[(((size_t)bh       * 32 + co) * 64 + sxg) * 32 + ky] = make_float2(a0x, a0y);
    g_Of[(((size_t)(bh + 8) * 32 + co) * 64 + sxg) * 32 + ky] = make_float2(a1x, a1y);
}

// ---- K4: inverse DFT along H (scalar radix-8); emits bf16 hi/lo planes ----
__global__ void __launch_bounds__(256) k_invH() {
    __shared__ float2 Ofs[64][8];
    __shared__ float2 E8is[8][8];
    int t = threadIdx.x;
    int bco = blockIdx.x >> 2, kq = blockIdx.x & 3;
    const float2* Op = g_Of + (size_t)bco * 64 * 32 + kq * 8;
    #pragma unroll
    for (int i = 0; i < 2; i++) {
        int idx = t + 256*i;
        Ofs[idx >> 3][idx & 7] = Op[(size_t)(idx >> 3) * 32 + (idx & 7)];
    }
    if (t < 64) ((float2*)E8is)[t] = g_E8i[t];
    __syncthreads();
    int v = t >> 3, k = t & 7;
    float2 gg[8];
    #pragma unroll
    for (int m = 0; m < 8; m++) {
        float gx = 0.f, gy = 0.f;
        #pragma unroll
        for (int j = 0; j < 8; j++) {
            int sx = m + 8*j;
            float2 o  = Ofs[sx][k];
            float2 tw = g_TV[sx * 32 + v];
            gx = fmaf(o.x, tw.x, fmaf( o.y, tw.y, gx));
            gy = fmaf(o.y, tw.x, fmaf(-o.x, tw.y, gy));
        }
        gg[m] = make_float2(gx, gy);
    }
    int col = kq * 8 + k;
    #pragma unroll
    for (int a = 0; a < 8; a++) {
        float tx = 0.f, ty = 0.f;
        #pragma unroll
        for (int m = 0; m < 8; m++) {
            float2 e = E8is[m][a];
            tx = fmaf(gg[m].x, e.x, fmaf(-gg[m].y, e.y, tx));
            ty = fmaf(gg[m].x, e.y, fmaf( gg[m].y, e.x, ty));
        }
        size_t row = (size_t)bco * 256 + v + 32 * a;
        __nv_bfloat16 hr, lr, hi, li;
        split_bf(tx, hr, lr); split_bf(ty, hi, li);
        *(uint32_t*)(g_TmpAh + row * 64 + 2 * col) = pack_bf(hr, hi);
        *(uint32_t*)(g_TmpAl + row * 64 + 2 * col) = pack_bf(lr, li);
    }
}

// ============== K5: inverse real DFT along W via mma.sync; A = pure memcpy ==============
#define IR_SMEM 73728
__global__ void __launch_bounds__(256) k_irfftW_m(float* __restrict__ out) {
    extern __shared__ unsigned char smem[];
    __nv_bfloat16* Ah = (__nv_bfloat16*)(smem);             // [128][72 pad]
    __nv_bfloat16* Al = (__nv_bfloat16*)(smem + 18432);
    __nv_bfloat16* Bh = (__nv_bfloat16*)(smem + 36864);
    __nv_bfloat16* Bl = (__nv_bfloat16*)(smem + 55296);
    int tid = threadIdx.x, lane = tid & 31, wid = tid >> 5;
    int g = lane >> 2, t4 = lane & 3;
    int rg = blockIdx.x >> 1, nh = blockIdx.x & 1;
    size_t rowBase = (size_t)rg * 128;

    // stage A: pure uint4 memcpy with pad (planes already bf16 in A layout)
    {
        const uint4* sh = (const uint4*)(g_TmpAh + rowBase * 64);
        const uint4* sl = (const uint4*)(g_TmpAl + rowBase * 64);
        #pragma unroll
        for (int i = 0; i < 4; i++) {
            int idx = tid + 256 * i;              // 1024 = 128 rows x 8 uint4
            int row = idx >> 3, c = idx & 7;
            *(uint4*)(Ah + row * 72 + c * 8) = sh[idx];
            *(uint4*)(Al + row * 72 + c * 8) = sl[idx];
        }
    }
    // stage B: constant basis half
    {
        const uint4* sh = ((const uint4*)g_BIh) + nh * 1152;
        const uint4* sl = ((const uint4*)g_BIl) + nh * 1152;
        uint4* dh = (uint4*)Bh; uint4* dl = (uint4*)Bl;
        for (int i = tid; i < 1152; i += 256) { dh[i] = sh[i]; dl[i] = sl[i]; }
    }
    __syncthreads();

    int m0 = (wid >> 1) * 32;
    int n0 = (wid & 1) * 64;
    float acc[2][8][4];
    #pragma unroll
    for (int mt = 0; mt < 2; mt++)
        #pragma unroll
        for (int nt = 0; nt < 8; nt++)
            #pragma unroll
            for (int i = 0; i < 4; i++) acc[mt][nt][i] = 0.f;

    #pragma unroll
    for (int ks = 0; ks < 4; ks++) {
        uint32_t ah[2][4], al[2][4];
        #pragma unroll
        for (int mt = 0; mt < 2; mt++) {
            int aoff = (m0 + mt * 16 + g) * 72 + ks * 16 + 2 * t4;
            ah[mt][0] = *(const uint32_t*)(Ah + aoff);
            ah[mt][1] = *(const uint32_t*)(Ah + aoff + 8 * 72);
            ah[mt][2] = *(const uint32_t*)(Ah + aoff + 8);
            ah[mt][3] = *(const uint32_t*)(Ah + aoff + 8 * 72 + 8);
            al[mt][0] = *(const uint32_t*)(Al + aoff);
            al[mt][1] = *(const uint32_t*)(Al + aoff + 8 * 72);
            al[mt][2] = *(const uint32_t*)(Al + aoff + 8);
            al[mt][3] = *(const uint32_t*)(Al + aoff + 8 * 72 + 8);
        }
        #pragma unroll
        for (int nt = 0; nt < 8; nt++) {
            int boff = (n0 + nt * 8 + g) * 72 + ks * 16 + 2 * t4;
            uint32_t bh[2], bl[2];
            bh[0] = *(const uint32_t*)(Bh + boff);
            bh[1] = *(const uint32_t*)(Bh + boff + 8);
            bl[0] = *(const uint32_t*)(Bl + boff);
            bl[1] = *(const uint32_t*)(Bl + boff + 8);
            #pragma unroll
            for (int mt = 0; mt < 2; mt++) {
                mma16816(acc[mt][nt], ah[mt], bh);
                mma16816(acc[mt][nt], ah[mt], bl);
                mma16816(acc[mt][nt], al[mt], bh);
            }
        }
    }
    #pragma unroll
    for (int mt = 0; mt < 2; mt++) {
        size_t r0 = rowBase + m0 + mt * 16 + g;
        #pragma unroll
        for (int nt = 0; nt < 8; nt++) {
            int col = nh * 128 + n0 + nt * 8 + 2 * t4;
            *(float2*)(out + r0 * 256 + col)       = make_float2(acc[mt][nt][0], acc[mt][nt][1]);
            *(float2*)(out + (r0 + 8) * 256 + col) = make_float2(acc[mt][nt][2], acc[mt][nt][3]);
        }
    }
}

extern "C" void kernel_launch(void* const* d_in, const int* in_sizes, int n_in,
                              void* d_out, int out_size) {
    const float* x   = (const float*)d_in[0];
    const float* fs  = (const float*)d_in[1];
    const float* w0  = (const float*)d_in[2];
    const float* w1  = (const float*)d_in[3];
    const float* we0 = (const float*)d_in[4];
    const float* we1 = (const float*)d_in[5];
    float* out = (float*)d_out;

    cudaFuncSetAttribute(k_fwdW_m,   cudaFuncAttributeMaxDynamicSharedMemorySize, FW_SMEM);
    cudaFuncSetAttribute(k_irfftW_m, cudaFuncAttributeMaxDynamicSharedMemorySize, IR_SMEM);

    k_init<<<158, 256>>>();
    k_wtrans<<<4096, 256>>>(w0, w1, we0, we1);
    k_fwdW_m<<<RTOT / 128, 256, FW_SMEM>>>(x);        // 1024 CTAs
    k_fwdH<<<Bsz * CIn * 4, 256>>>();                 // 2048 CTAs
    k_mix<<<2 * 1024, 256>>>(fs);                     // 2048 CTAs
    k_invH<<<Bsz * COn * 4, 256>>>();                 // 2048 CTAs
    k_irfftW_m<<<RTOT / 64, 256, IR_SMEM>>>(out);     // 2048 CTAs
}

// round 15
// speedup vs baseline: 1.0505x; 1.0039x over previous
#include <cuda_runtime.h>
#include <cuda_bf16.h>
#include <math.h>
#include <stdint.h>

// Problem constants
#define Bsz 16
#define CIn 32
#define COn 32
#define Hn  256
#define Wn  256
#define KM  32
#define SXn 64
#define RTOT (Bsz*CIn*Hn)   // 131072 rows

// ============================ tables ============================
__device__ float4 g_TV2[32*32];   // [sxp][v] packed (TV[sxp][v], TV[sxp+32][v]); TV=(cos,-sin)
__device__ float2 g_E8 [8*8];
__device__ float2 g_E8i[8*8];
// fwdW basis  [kc(4)][n(64)][72pad]  bf16 hi/lo (smem-staged per chunk)
__device__ __align__(16) __nv_bfloat16 g_BWh[4*64*72], g_BWl[4*64*72];
// irfft basis [nh(2)][wn(128)][72pad] bf16 hi/lo (smem-staged)
__device__ __align__(16) __nv_bfloat16 g_BIh[2*128*72], g_BIl[2*128*72];

// ============================ scratch ============================
__device__ float2 g_Xw[(size_t)RTOT*KM];          // fwdW out [row][k]
__device__ float2 g_Xf[(size_t)Bsz*CIn*SXn*KM];   // fwdH out [bci][sx][k]
__device__ float2 g_Of[(size_t)Bsz*COn*SXn*KM];   // mix out  [bco][sx][k]
// invH out, bf16 hi/lo planes in irfftW's A layout: [row][64] = interleaved (re,im) per ky
__device__ __align__(16) __nv_bfloat16 g_TmpAh[(size_t)Bsz*COn*Hn*64];
__device__ __align__(16) __nv_bfloat16 g_TmpAl[(size_t)Bsz*COn*Hn*64];
__device__ float2 g_Wt [2*1024*1024];
__device__ float2 g_Wet[2*1024*1024];

// ============================ helpers ============================
__device__ __forceinline__ uint32_t pack_bf(__nv_bfloat16 a, __nv_bfloat16 b) {
    return (uint32_t)__bfloat16_as_ushort(a) | ((uint32_t)__bfloat16_as_ushort(b) << 16);
}
__device__ __forceinline__ void split_bf(float v, __nv_bfloat16& h, __nv_bfloat16& l) {
    h = __float2bfloat16(v);
    l = __float2bfloat16(v - __bfloat162float(h));
}
__device__ __forceinline__ void mma16816(float* c, const uint32_t* a, const uint32_t* b) {
    asm volatile("mma.sync.aligned.m16n8k16.row.col.f32.bf16.bf16.f32 "
        "{%0,%1,%2,%3}, {%4,%5,%6,%7}, {%8,%9}, {%0,%1,%2,%3};"
        : "+f"(c[0]), "+f"(c[1]), "+f"(c[2]), "+f"(c[3])
        : "r"(a[0]), "r"(a[1]), "r"(a[2]), "r"(a[3]), "r"(b[0]), "r"(b[1]));
}

#define SEG 18432   // 4*64*72 == 2*128*72

__global__ void k_init() {
    int t = blockIdx.x * blockDim.x + threadIdx.x;
    if (t < 1024) {                     // g_TV2 packed (sxp, sxp+32)
        int sxp = t >> 5, v = t & 31;
        float s0, c0, s1, c1;
        sincospif((float)(sxp * v) / 128.0f, &s0, &c0);
        int kx1 = 224 + sxp;            // kx for sxp+32
        sincospif((float)(kx1 * v) / 128.0f, &s1, &c1);
        g_TV2[t] = make_float4(c0, -s0, c1, -s1);
    }
    int t1 = t - 1024;
    if (t1 >= 0 && t1 < 64) {           // E8 / E8i
        int m = t1 >> 3, a = t1 & 7;
        float s, c; sincospif((float)(m * a) / 4.0f, &s, &c);
        g_E8 [t1] = make_float2(c, -s);
        g_E8i[t1] = make_float2(c,  s);
    }
    int t2 = t1 - 64;
    if (t2 >= 0 && t2 < SEG) {          // fwdW basis
        int kc = t2 / (64*72);
        int rem = t2 % (64*72);
        int n = rem / 72, kk = rem % 72;
        float v = 0.f;
        if (kk < 64) {
            int w = kc * 64 + kk;
            float s, c; sincospif((float)((n >> 1) * w) / 128.0f, &s, &c);
            v = (n & 1) ? -s : c;
        }
        __nv_bfloat16 h, l; split_bf(v, h, l);
        g_BWh[t2] = h; g_BWl[t2] = l;
    }
    int t3 = t2 - SEG;
    if (t3 >= 0 && t3 < SEG) {          // irfft basis
        int nh = t3 / (128*72);
        int rem = t3 % (128*72);
        int wn = rem / 72, j = rem % 72;
        float v = 0.f;
        if (j < 64) {
            int w = nh * 128 + wn;
            int q = j >> 1;
            float s, c; sincospif((float)(q * w) / 128.0f, &s, &c);
            float alpha = ((q == 0) ? 1.0f : 2.0f) * (1.0f / 256.0f);
            v = (j & 1) ? -alpha * s : alpha * c;
        }
        __nv_bfloat16 h, l; split_bf(v, h, l);
        g_BIh[t3] = h; g_BIl[t3] = l;
    }
}

// ---- K0b: transpose weights [p][kxy] -> [kxy][p] ----
__global__ void __launch_bounds__(256) k_wtrans(const float* __restrict__ w0,
                                                const float* __restrict__ w1,
                                                const float* __restrict__ we0,
                                                const float* __restrict__ we1) {
    __shared__ float2 sm[32][33];
    int bid = blockIdx.x;
    int arr = bid >> 10;
    int tile = bid & 1023;
    int I = tile >> 5, J = tile & 31;
    const float2* src = (const float2*)((arr == 0) ? w0 : (arr == 1) ? w1 : (arr == 2) ? we0 : we1);
    float2* dst = (arr < 2) ? (g_Wt + (size_t)arr * 1024 * 1024)
                            : (g_Wet + (size_t)(arr - 2) * 1024 * 1024);
    int t = threadIdx.x;
    int c = t & 31, rq = t >> 5;
    #pragma unroll
    for (int i = 0; i < 4; i++)
        sm[rq + 8 * i][c] = src[(size_t)(I * 32 + rq + 8 * i) * 1024 + J * 32 + c];
    __syncthreads();
    #pragma unroll
    for (int i = 0; i < 4; i++)
        dst[(size_t)(J * 32 + rq + 8 * i) * 1024 + I * 32 + c] = sm[c][rq + 8 * i];
}

// ============== K1: fwd DFT along W via mma.sync ==============
#define FW_SMEM 55296
__global__ void __launch_bounds__(256) k_fwdW_m(const float* __restrict__ x) {
    extern __shared__ unsigned char smem[];
    __nv_bfloat16* Ah = (__nv_bfloat16*)(smem);
    __nv_bfloat16* Al = (__nv_bfloat16*)(smem + 18432);
    __nv_bfloat16* Bh = (__nv_bfloat16*)(smem + 36864);
    __nv_bfloat16* Bl = (__nv_bfloat16*)(smem + 46080);
    int tid = threadIdx.x, lane = tid & 31, wid = tid >> 5;
    int g = lane >> 2, t4 = lane & 3;
    size_t rowBase = (size_t)blockIdx.x * 128;
    int m0 = wid * 16;
    float acc[8][4];
    #pragma unroll
    for (int nt = 0; nt < 8; nt++)
        #pragma unroll
        for (int i = 0; i < 4; i++) acc[nt][i] = 0.f;

    const float4* xg = (const float4*)x;
    for (int kc = 0; kc < 4; kc++) {
        __syncthreads();
        #pragma unroll
        for (int i = 0; i < 8; i++) {
            int idx = tid + 256 * i;
            int r = idx >> 4, c4 = idx & 15;
            float4 v = xg[(rowBase + r) * 64 + kc * 16 + c4];
            __nv_bfloat16 h0, h1, h2, h3, l0, l1, l2, l3;
            split_bf(v.x, h0, l0); split_bf(v.y, h1, l1);
            split_bf(v.z, h2, l2); split_bf(v.w, h3, l3);
            *(uint2*)(Ah + r * 72 + c4 * 4) = make_uint2(pack_bf(h0, h1), pack_bf(h2, h3));
            *(uint2*)(Al + r * 72 + c4 * 4) = make_uint2(pack_bf(l0, l1), pack_bf(l2, l3));
        }
        {
            const uint4* sh = ((const uint4*)g_BWh) + kc * 576;
            const uint4* sl = ((const uint4*)g_BWl) + kc * 576;
            uint4* dh = (uint4*)Bh; uint4* dl = (uint4*)Bl;
            for (int i = tid; i < 576; i += 256) { dh[i] = sh[i]; dl[i] = sl[i]; }
        }
        __syncthreads();
        #pragma unroll
        for (int ks = 0; ks < 4; ks++) {
            int aoff = (m0 + g) * 72 + ks * 16 + 2 * t4;
            uint32_t ah[4], al[4];
            ah[0] = *(const uint32_t*)(Ah + aoff);
            ah[1] = *(const uint32_t*)(Ah + aoff + 8 * 72);
            ah[2] = *(const uint32_t*)(Ah + aoff + 8);
            ah[3] = *(const uint32_t*)(Ah + aoff + 8 * 72 + 8);
            al[0] = *(const uint32_t*)(Al + aoff);
            al[1] = *(const uint32_t*)(Al + aoff + 8 * 72);
            al[2] = *(const uint32_t*)(Al + aoff + 8);
            al[3] = *(const uint32_t*)(Al + aoff + 8 * 72 + 8);
            #pragma unroll
            for (int nt = 0; nt < 8; nt++) {
                int boff = (nt * 8 + g) * 72 + ks * 16 + 2 * t4;
                uint32_t bh[2], bl[2];
                bh[0] = *(const uint32_t*)(Bh + boff);
                bh[1] = *(const uint32_t*)(Bh + boff + 8);
                bl[0] = *(const uint32_t*)(Bl + boff);
                bl[1] = *(const uint32_t*)(Bl + boff + 8);
                mma16816(acc[nt], ah, bh);
                mma16816(acc[nt], ah, bl);
                mma16816(acc[nt], al, bh);
            }
        }
    }
    float2* gx = (float2*)g_Xw;
    #pragma unroll
    for (int nt = 0; nt < 8; nt++) {
        int col = nt * 4 + t4;
        gx[(rowBase + m0 + g) * 32 + col]     = make_float2(acc[nt][0], acc[nt][1]);
        gx[(rowBase + m0 + g + 8) * 32 + col] = make_float2(acc[nt][2], acc[nt][3]);
    }
}

// ---- K2: fwd DFT along H (scalar radix-8 + packed TV2 loads) ----
__global__ void __launch_bounds__(256) k_fwdH() {
    __shared__ float2 Xs[256][8];
    __shared__ float2 Ys[32][8][8];
    __shared__ float2 E8s[8][8];
    int t = threadIdx.x;
    int bci = blockIdx.x >> 2, kq = blockIdx.x & 3;
    const float2* Xp = g_Xw + (size_t)bci * 256 * 32 + kq * 8;
    #pragma unroll
    for (int i = 0; i < 8; i++) {
        int idx = t + 256*i;
        Xs[idx >> 3][idx & 7] = Xp[(size_t)(idx >> 3) * 32 + (idx & 7)];
    }
    if (t < 64) ((float2*)E8s)[t] = g_E8[t];
    __syncthreads();
    int v = t >> 3, k = t & 7;
    {
        float2 xa[8];
        #pragma unroll
        for (int a = 0; a < 8; a++) xa[a] = Xs[v + 32*a][k];
        #pragma unroll
        for (int m = 0; m < 8; m++) {
            float yr = 0.f, yi = 0.f;
            #pragma unroll
            for (int a = 0; a < 8; a++) {
                float2 e = E8s[m][a];
                yr = fmaf(xa[a].x, e.x, fmaf(-xa[a].y, e.y, yr));
                yi = fmaf(xa[a].x, e.y, fmaf( xa[a].y, e.x, yi));
            }
            Ys[v][m][k] = make_float2(yr, yi);
        }
    }
    __syncthreads();
    int k2 = t & 7, sx2 = t >> 3;
    int m = sx2 & 7;
    float a0x = 0.f, a0y = 0.f, a1x = 0.f, a1y = 0.f;
    #pragma unroll 8
    for (int vv = 0; vv < 32; vv++) {
        float2 y  = Ys[vv][m][k2];
        float4 tp = g_TV2[sx2 * 32 + vv];   // (t0.re, t0.im, t1.re, t1.im) — one 16B load
        a0x = fmaf(y.x, tp.x, fmaf(-y.y, tp.y, a0x));
        a0y = fmaf(y.x, tp.y, fmaf( y.y, tp.x, a0y));
        a1x = fmaf(y.x, tp.z, fmaf(-y.y, tp.w, a1x));
        a1y = fmaf(y.x, tp.w, fmaf( y.y, tp.z, a1y));
    }
    const float nrm = 1.0f / 256.0f;
    g_Xf[((size_t)bci * 64 + sx2)      * 32 + kq * 8 + k2] = make_float2(a0x * nrm, a0y * nrm);
    g_Xf[((size_t)bci * 64 + sx2 + 32) * 32 + kq * 8 + k2] = make_float2(a1x * nrm, a1y * nrm);
}

// ---- K3: channel mixing ----
__global__ void __launch_bounds__(256) k_mix(const float* __restrict__ fs) {
    __shared__ float2 Ws[1024];
    __shared__ float2 Wes[1024];
    __shared__ float2 Xs[16][32];
    __shared__ float  ssm[16];
    int bid = blockIdx.x;
    int r = bid >> 10, kxy = bid & 1023;
    int kx = kxy >> 5, ky = kxy & 31;
    int sxg = r * 32 + kx;
    const float2* Wp  = g_Wt  + ((size_t)r << 20) + ((size_t)kxy << 10);
    const float2* Wep = g_Wet + ((size_t)r << 20) + ((size_t)kxy << 10);
    int t = threadIdx.x;
    #pragma unroll
    for (int i = 0; i < 4; i++) {
        Ws [t + 256*i] = Wp [t + 256*i];
        Wes[t + 256*i] = Wep[t + 256*i];
    }
    #pragma unroll
    for (int i = 0; i < 2; i++) {
        int p = t + 256*i;
        Xs[p >> 5][p & 31] = g_Xf[((size_t)p * 64 + sxg) * 32 + ky];
    }
    if (t < 16) {
        int idx;
        if (kx < 8 && ky < 8)        idx = 0;
        else if (kx < 16 && ky < 16) idx = (kx < 8) ? 1 : ((ky < 8) ? 2 : 3);
        else                         idx = (kx < 16) ? 4 : ((ky < 16) ? 5 : 6);
        ssm[t] = fs[t * 7 + idx];
    }
    __syncthreads();
    int co = t & 31, bh = t >> 5;
    float sb0 = ssm[bh], sb1 = ssm[bh + 8];
    float a0x = 0.f, a0y = 0.f, a1x = 0.f, a1y = 0.f;
    #pragma unroll 8
    for (int ci = 0; ci < 32; ci++) {
        float2 w  = Ws [ci * 32 + co];
        float2 we = Wes[ci * 32 + co];
        float2 x0 = Xs[bh][ci];
        float2 x1 = Xs[bh + 8][ci];
        float wr0 = fmaf(sb0, we.x, w.x), wi0 = fmaf(sb0, we.y, w.y);
        float wr1 = fmaf(sb1, we.x, w.x), wi1 = fmaf(sb1, we.y, w.y);
        a0x = fmaf(x0.x, wr0, fmaf(-x0.y, wi0, a0x));
        a0y = fmaf(x0.x, wi0, fmaf( x0.y, wr0, a0y));
        a1x = fmaf(x1.x, wr1, fmaf(-x1.y, wi1, a1x));
        a1y = fmaf(x1.x, wi1, fmaf( x1.y, wr1, a1y));
    }
    g_Of[(((size_t)bh       * 32 + co) * 64 + sxg) * 32 + ky] = make_float2(a0x, a0y);
    g_Of[(((size_t)(bh + 8) * 32 + co) * 64 + sxg) * 32 + ky] = make_float2(a1x, a1y);
}

// ---- K4: inverse DFT along H (scalar radix-8, packed TV2 loads); emits bf16 planes ----
__global__ void __launch_bounds__(256) k_invH() {
    __shared__ float2 Ofs[64][8];
    __shared__ float2 E8is[8][8];
    int t = threadIdx.x;
    int bco = blockIdx.x >> 2, kq = blockIdx.x & 3;
    const float2* Op = g_Of + (size_t)bco * 64 * 32 + kq * 8;
    #pragma unroll
    for (int i = 0; i < 2; i++) {
        int idx = t + 256*i;
        Ofs[idx >> 3][idx & 7] = Op[(size_t)(idx >> 3) * 32 + (idx & 7)];
    }
    if (t < 64) ((float2*)E8is)[t] = g_E8i[t];
    __syncthreads();
    int v = t >> 3, k = t & 7;
    float2 gg[8];
    #pragma unroll
    for (int m = 0; m < 8; m++) {
        float gx = 0.f, gy = 0.f;
        // pairs (sxp, sxp+32) with sxp = m + 8*j2 cover sx = m + 8*j, j=0..7
        #pragma unroll
        for (int j2 = 0; j2 < 4; j2++) {
            int sxp = m + 8 * j2;
            float4 tp = g_TV2[sxp * 32 + v];     // one 16B load for both halves
            float2 o0 = Ofs[sxp][k];
            float2 o1 = Ofs[sxp + 32][k];
            gx = fmaf(o0.x, tp.x, fmaf( o0.y, tp.y, gx));
            gy = fmaf(o0.y, tp.x, fmaf(-o0.x, tp.y, gy));
            gx = fmaf(o1.x, tp.z, fmaf( o1.y, tp.w, gx));
            gy = fmaf(o1.y, tp.z, fmaf(-o1.x, tp.w, gy));
        }
        gg[m] = make_float2(gx, gy);
    }
    int col = kq * 8 + k;
    #pragma unroll
    for (int a = 0; a < 8; a++) {
        float tx = 0.f, ty = 0.f;
        #pragma unroll
        for (int m = 0; m < 8; m++) {
            float2 e = E8is[m][a];
            tx = fmaf(gg[m].x, e.x, fmaf(-gg[m].y, e.y, tx));
            ty = fmaf(gg[m].x, e.y, fmaf( gg[m].y, e.x, ty));
        }
        size_t row = (size_t)bco * 256 + v + 32 * a;
        __nv_bfloat16 hr, lr, hi, li;
        split_bf(tx, hr, lr); split_bf(ty, hi, li);
        *(uint32_t*)(g_TmpAh + row * 64 + 2 * col) = pack_bf(hr, hi);
        *(uint32_t*)(g_TmpAl + row * 64 + 2 * col) = pack_bf(lr, li);
    }
}

// ============== K5: inverse real DFT along W via mma.sync; A = pure memcpy ==============
#define IR_SMEM 73728
__global__ void __launch_bounds__(256) k_irfftW_m(float* __restrict__ out) {
    extern __shared__ unsigned char smem[];
    __nv_bfloat16* Ah = (__nv_bfloat16*)(smem);             // [128][72 pad]
    __nv_bfloat16* Al = (__nv_bfloat16*)(smem + 18432);
    __nv_bfloat16* Bh = (__nv_bfloat16*)(smem + 36864);
    __nv_bfloat16* Bl = (__nv_bfloat16*)(smem + 55296);
    int tid = threadIdx.x, lane = tid & 31, wid = tid >> 5;
    int g = lane >> 2, t4 = lane & 3;
    int rg = blockIdx.x >> 1, nh = blockIdx.x & 1;
    size_t rowBase = (size_t)rg * 128;

    // stage A: pure uint4 memcpy with pad (planes already bf16 in A layout)
    {
        const uint4* sh = (const uint4*)(g_TmpAh + rowBase * 64);
        const uint4* sl = (const uint4*)(g_TmpAl + rowBase * 64);
        #pragma unroll
        for (int i = 0; i < 4; i++) {
            int idx = tid + 256 * i;              // 1024 = 128 rows x 8 uint4
            int row = idx >> 3, c = idx & 7;
            *(uint4*)(Ah + row * 72 + c * 8) = sh[idx];
            *(uint4*)(Al + row * 72 + c * 8) = sl[idx];
        }
    }
    // stage B: constant basis half
    {
        const uint4* sh = ((const uint4*)g_BIh) + nh * 1152;
        const uint4* sl = ((const uint4*)g_BIl) + nh * 1152;
        uint4* dh = (uint4*)Bh; uint4* dl = (uint4*)Bl;
        for (int i = tid; i < 1152; i += 256) { dh[i] = sh[i]; dl[i] = sl[i]; }
    }
    __syncthreads();

    int m0 = (wid >> 1) * 32;
    int n0 = (wid & 1) * 64;
    float acc[2][8][4];
    #pragma unroll
    for (int mt = 0; mt < 2; mt++)
        #pragma unroll
        for (int nt = 0; nt < 8; nt++)
            #pragma unroll
            for (int i = 0; i < 4; i++) acc[mt][nt][i] = 0.f;

    #pragma unroll
    for (int ks = 0; ks < 4; ks++) {
        uint32_t ah[2][4], al[2][4];
        #pragma unroll
        for (int mt = 0; mt < 2; mt++) {
            int aoff = (m0 + mt * 16 + g) * 72 + ks * 16 + 2 * t4;
            ah[mt][0] = *(const uint32_t*)(Ah + aoff);
            ah[mt][1] = *(const uint32_t*)(Ah + aoff + 8 * 72);
            ah[mt][2] = *(const uint32_t*)(Ah + aoff + 8);
            ah[mt][3] = *(const uint32_t*)(Ah + aoff + 8 * 72 + 8);
            al[mt][0] = *(const uint32_t*)(Al + aoff);
            al[mt][1] = *(const uint32_t*)(Al + aoff + 8 * 72);
            al[mt][2] = *(const uint32_t*)(Al + aoff + 8);
            al[mt][3] = *(const uint32_t*)(Al + aoff + 8 * 72 + 8);
        }
        #pragma unroll
        for (int nt = 0; nt < 8; nt++) {
            int boff = (n0 + nt * 8 + g) * 72 + ks * 16 + 2 * t4;
            uint32_t bh[2], bl[2];
            bh[0] = *(const uint32_t*)(Bh + boff);
            bh[1] = *(const uint32_t*)(Bh + boff + 8);
            bl[0] = *(const uint32_t*)(Bl + boff);
            bl[1] = *(const uint32_t*)(Bl + boff + 8);
            #pragma unroll
            for (int mt = 0; mt < 2; mt++) {
                mma16816(acc[mt][nt], ah[mt], bh);
                mma16816(acc[mt][nt], ah[mt], bl);
                mma16816(acc[mt][nt], al[mt], bh);
            }
        }
    }
    #pragma unroll
    for (int mt = 0; mt < 2; mt++) {
        size_t r0 = rowBase + m0 + mt * 16 + g;
        #pragma unroll
        for (int nt = 0; nt < 8; nt++) {
            int col = nh * 128 + n0 + nt * 8 + 2 * t4;
            *(float2*)(out + r0 * 256 + col)       = make_float2(acc[mt][nt][0], acc[mt][nt][1]);
            *(float2*)(out + (r0 + 8) * 256 + col) = make_float2(acc[mt][nt][2], acc[mt][nt][3]);
        }
    }
}

extern "C" void kernel_launch(void* const* d_in, const int* in_sizes, int n_in,
                              void* d_out, int out_size) {
    const float* x   = (const float*)d_in[0];
    const float* fs  = (const float*)d_in[1];
    const float* w0  = (const float*)d_in[2];
    const float* w1  = (const float*)d_in[3];
    const float* we0 = (const float*)d_in[4];
    const float* we1 = (const float*)d_in[5];
    float* out = (float*)d_out;

    cudaFuncSetAttribute(k_fwdW_m,   cudaFuncAttributeMaxDynamicSharedMemorySize, FW_SMEM);
    cudaFuncSetAttribute(k_irfftW_m, cudaFuncAttributeMaxDynamicSharedMemorySize, IR_SMEM);

    k_init<<<154, 256>>>();
    k_wtrans<<<4096, 256>>>(w0, w1, we0, we1);
    k_fwdW_m<<<RTOT / 128, 256, FW_SMEM>>>(x);        // 1024 CTAs
    k_fwdH<<<Bsz * CIn * 4, 256>>>();                 // 2048 CTAs
    k_mix<<<2 * 1024, 256>>>(fs);                     // 2048 CTAs
    k_invH<<<Bsz * COn * 4, 256>>>();                 // 2048 CTAs
    k_irfftW_m<<<RTOT / 64, 256, IR_SMEM>>>(out);     // 2048 CTAs
}